// round 6
// baseline (speedup 1.0000x reference)
#include <cuda_runtime.h>
#include <cuda_bf16.h>
#include <math.h>
#include <stdint.h>

#define NN 100000
#define EE 1600000
#define D  128
#define HEADS 4
#define CH 32
#define NEG_SLOPE 0.2f
#define CAP 64                         // deg ~ Poisson(16); P(deg>64) ~ 2e-22
#define NB_SCAN ((NN + 1023) / 1024)   // 98

// ---------------- scratch ------------------------------------------------------
__device__ float g_bufA[NN * D];
__device__ float g_bufB[NN * D];
__device__ float g_xr[NN * D];
__device__ float g_ss[NN * HEADS];
__device__ float g_sd[NN * HEADS];
__device__ int   g_deg[NN];            // statically zero; agg2 re-zeroes each launch
__device__ int   g_offs[NN + 1];
__device__ int   g_cursor[NN];
__device__ int   g_sorted_src[EE];
__device__ int   g_bsum[NB_SCAN];
__device__ int   g_bpre[NB_SCAN];

// ---------------- edge dtype detection (per-block inline) -----------------------
__device__ __forceinline__ int detect_s64(const void* ei, int* smem_flag) {
    if (threadIdx.x == 0) *smem_flag = 1;
    __syncthreads();
    if (threadIdx.x < 256)
        if (((const unsigned int*)ei)[2 * threadIdx.x + 1] != 0u) *smem_flag = 0;
    __syncthreads();
    return *smem_flag;
}

// ---------------- counting sort --------------------------------------------------
__global__ void __launch_bounds__(256) count_kernel(const void* __restrict__ ei) {
    __shared__ int s64s;
    int s64 = detect_s64(ei, &s64s);
    int i = blockIdx.x * blockDim.x + threadIdx.x;
    if (i >= EE) return;
    int d = s64 ? (int)((const long long*)ei)[(long long)EE + i]
                : ((const int*)ei)[EE + i];
    atomicAdd(&g_deg[d], 1);
}

__global__ void __launch_bounds__(256) scan_k1() {
    __shared__ int sm[256];
    int b = blockIdx.x, tid = threadIdx.x;
    int base = b * 1024 + tid * 4;
    int s = 0;
#pragma unroll
    for (int j = 0; j < 4; ++j) {
        int idx = base + j;
        if (idx < NN) s += g_deg[idx];
    }
    sm[tid] = s;
    __syncthreads();
    for (int off = 128; off; off >>= 1) {
        if (tid < off) sm[tid] += sm[tid + off];
        __syncthreads();
    }
    if (tid == 0) g_bsum[b] = sm[0];
}

__global__ void scan_k2() {
    __shared__ int sm[128];
    int tid = threadIdx.x;
    sm[tid] = (tid < NB_SCAN) ? g_bsum[tid] : 0;
    __syncthreads();
    for (int off = 1; off < 128; off <<= 1) {
        int v = (tid >= off) ? sm[tid - off] : 0;
        __syncthreads();
        sm[tid] += v;
        __syncthreads();
    }
    if (tid < NB_SCAN) g_bpre[tid] = (tid == 0) ? 0 : sm[tid - 1];
    if (tid == 0) g_offs[NN] = EE;
}

__global__ void __launch_bounds__(256) scan_k3() {
    __shared__ int sm[256];
    int b = blockIdx.x, tid = threadIdx.x;
    int base = b * 1024 + tid * 4;
    int v[4];
#pragma unroll
    for (int j = 0; j < 4; ++j) {
        int idx = base + j;
        v[j] = (idx < NN) ? g_deg[idx] : 0;
    }
    int tot = v[0] + v[1] + v[2] + v[3];
    sm[tid] = tot;
    __syncthreads();
    for (int off = 1; off < 256; off <<= 1) {
        int x = (tid >= off) ? sm[tid - off] : 0;
        __syncthreads();
        sm[tid] += x;
        __syncthreads();
    }
    int run = g_bpre[b] + ((tid == 0) ? 0 : sm[tid - 1]);
#pragma unroll
    for (int j = 0; j < 4; ++j) {
        int idx = base + j;
        if (idx < NN) {
            g_offs[idx]   = run;
            g_cursor[idx] = run;
            run += v[j];
        }
    }
}

__global__ void __launch_bounds__(256) scatter_kernel(const void* __restrict__ ei) {
    __shared__ int s64s;
    int s64 = detect_s64(ei, &s64s);
    int i = blockIdx.x * blockDim.x + threadIdx.x;
    if (i >= EE) return;
    int s, d;
    if (s64) {
        s = (int)((const long long*)ei)[i];
        d = (int)((const long long*)ei)[(long long)EE + i];
    } else {
        s = ((const int*)ei)[i];
        d = ((const int*)ei)[EE + i];
    }
    int pos = atomicAdd(&g_cursor[d], 1);
    g_sorted_src[pos] = s;
}

// ---------------- tf32 tensor-core GEMM (occupancy-optimized) --------------------
__device__ __forceinline__ float to_tf32(float x) {
    uint32_t u;
    asm("cvt.rna.tf32.f32 %0, %1;" : "=r"(u) : "f"(x));
    return __uint_as_float(u);
}

#define MMA_TF32(c, av, bv)                                                  \
    asm volatile(                                                            \
        "mma.sync.aligned.m16n8k8.row.col.f32.tf32.tf32.f32 "                \
        "{%0,%1,%2,%3},{%4,%5,%6,%7},{%8,%9},{%0,%1,%2,%3};"                 \
        : "+f"((c)[0]), "+f"((c)[1]), "+f"((c)[2]), "+f"((c)[3])             \
        : "r"((av)[0]), "r"((av)[1]), "r"((av)[2]), "r"((av)[3]),            \
          "r"((bv)[0]), "r"((bv)[1]))

// block tile 128(M) x 64(N); grid = (ceil(N/128), 2); 256 thr = 8 warps 4(M)x2(N);
// warp tile 32x32 (acc = 32 regs/thread) => 3 CTAs/SM
template<bool SCORES>
__global__ void __launch_bounds__(256, 3) gemm_tc_kernel(
    const float* __restrict__ A, const float* __restrict__ W,
    const float* __restrict__ a_src, const float* __restrict__ a_dst,
    float* __restrict__ out, float* __restrict__ ssrc, float* __restrict__ sdst)
{
    __shared__ float AsT[32][132];   // [k][m]
    __shared__ float Ws[32][68];     // [k][n], 64 cols padded

    const int tid  = threadIdx.x;
    const int warp = tid >> 5, lane = tid & 31;
    const int g = lane >> 2, t = lane & 3;
    const int wm = warp >> 1;          // 0..3
    const int wn = warp & 1;           // 0..1
    const int m0 = wm * 32, n0 = wn * 32;
    const int row0  = blockIdx.x * 128;
    const int ncol0 = blockIdx.y * 64;
    const int head  = blockIdx.y * 2 + wn;   // warp tile spans exactly one head

    float acc[2][4][4];
#pragma unroll
    for (int i = 0; i < 2; ++i)
#pragma unroll
        for (int j = 0; j < 4; ++j)
#pragma unroll
            for (int k = 0; k < 4; ++k) acc[i][j][k] = 0.f;

    for (int kc = 0; kc < D; kc += 32) {
        // A chunk: 128 rows x 32 k -> AsT[k][m]
#pragma unroll
        for (int it = 0; it < 4; ++it) {
            int idx = tid + it * 256;    // 0..1023
            int r = idx >> 3, q = idx & 7;
            int row = row0 + r;
            float4 v = make_float4(0.f, 0.f, 0.f, 0.f);
            if (row < NN) v = *(const float4*)&A[(long long)row * D + kc + q * 4];
            AsT[q * 4 + 0][r] = to_tf32(v.x);
            AsT[q * 4 + 1][r] = to_tf32(v.y);
            AsT[q * 4 + 2][r] = to_tf32(v.z);
            AsT[q * 4 + 3][r] = to_tf32(v.w);
        }
        // W chunk: 32 k x 64 n
#pragma unroll
        for (int it = 0; it < 2; ++it) {
            int idx = tid + it * 256;    // 0..511
            int kr = idx >> 4;           // 0..31
            int c4 = idx & 15;           // 0..15
            float4 v = *(const float4*)&W[(kc + kr) * D + ncol0 + c4 * 4];
            Ws[kr][c4 * 4 + 0] = to_tf32(v.x);
            Ws[kr][c4 * 4 + 1] = to_tf32(v.y);
            Ws[kr][c4 * 4 + 2] = to_tf32(v.z);
            Ws[kr][c4 * 4 + 3] = to_tf32(v.w);
        }
        __syncthreads();
#pragma unroll
        for (int ks = 0; ks < 32; ks += 8) {
            uint32_t a[2][4], b[4][2];
#pragma unroll
            for (int mt = 0; mt < 2; ++mt) {
                int mr = m0 + mt * 16 + g;
                a[mt][0] = __float_as_uint(AsT[ks + t][mr]);
                a[mt][1] = __float_as_uint(AsT[ks + t][mr + 8]);
                a[mt][2] = __float_as_uint(AsT[ks + t + 4][mr]);
                a[mt][3] = __float_as_uint(AsT[ks + t + 4][mr + 8]);
            }
#pragma unroll
            for (int nt = 0; nt < 4; ++nt) {
                int nc = n0 + nt * 8 + g;
                b[nt][0] = __float_as_uint(Ws[ks + t][nc]);
                b[nt][1] = __float_as_uint(Ws[ks + t + 4][nc]);
            }
#pragma unroll
            for (int mt = 0; mt < 2; ++mt)
#pragma unroll
                for (int nt = 0; nt < 4; ++nt)
                    MMA_TF32(acc[mt][nt], a[mt], b[nt]);
        }
        __syncthreads();
    }

    // epilogue: store + fused per-head scores
    float2 asv[4], adv[4];
    if (SCORES) {
#pragma unroll
        for (int nt = 0; nt < 4; ++nt) {
            int c = nt * 8 + 2 * t;      // channel within head
            asv[nt] = make_float2(a_src[head * CH + c], a_src[head * CH + c + 1]);
            adv[nt] = make_float2(a_dst[head * CH + c], a_dst[head * CH + c + 1]);
        }
    }
#pragma unroll
    for (int mt = 0; mt < 2; ++mt) {
        int r_lo = row0 + m0 + mt * 16 + g;
        int r_hi = r_lo + 8;
        float su_lo = 0.f, du_lo = 0.f, su_hi = 0.f, du_hi = 0.f;
#pragma unroll
        for (int nt = 0; nt < 4; ++nt) {
            int col = ncol0 + n0 + nt * 8 + 2 * t;
            if (r_lo < NN)
                *(float2*)&out[(long long)r_lo * D + col] =
                    make_float2(acc[mt][nt][0], acc[mt][nt][1]);
            if (r_hi < NN)
                *(float2*)&out[(long long)r_hi * D + col] =
                    make_float2(acc[mt][nt][2], acc[mt][nt][3]);
            if (SCORES) {
                su_lo += acc[mt][nt][0] * asv[nt].x + acc[mt][nt][1] * asv[nt].y;
                du_lo += acc[mt][nt][0] * adv[nt].x + acc[mt][nt][1] * adv[nt].y;
                su_hi += acc[mt][nt][2] * asv[nt].x + acc[mt][nt][3] * asv[nt].y;
                du_hi += acc[mt][nt][2] * adv[nt].x + acc[mt][nt][3] * adv[nt].y;
            }
        }
        if (SCORES) {
#pragma unroll
            for (int off = 1; off <= 2; off <<= 1) {
                su_lo += __shfl_xor_sync(0xffffffffu, su_lo, off);
                du_lo += __shfl_xor_sync(0xffffffffu, du_lo, off);
                su_hi += __shfl_xor_sync(0xffffffffu, su_hi, off);
                du_hi += __shfl_xor_sync(0xffffffffu, du_hi, off);
            }
            if (t == 0) {
                if (r_lo < NN) { ssrc[r_lo * HEADS + head] = su_lo; sdst[r_lo * HEADS + head] = du_lo; }
                if (r_hi < NN) { ssrc[r_hi * HEADS + head] = su_hi; sdst[r_hi * HEADS + head] = du_hi; }
            }
        }
    }
}

// ---------------- softmax + aggregation (no max shift; packed (src,e) planes) ---
__device__ __forceinline__ float lrelu(float v) { return v > 0.f ? v : NEG_SLOPE * v; }

template<int LAYER>
__global__ void __launch_bounds__(256) agg_kernel(
    const float* __restrict__ h,
    const float* __restrict__ ss,
    const float* __restrict__ sd,
    const float* __restrict__ bias,
    float* __restrict__ out,
    const float* __restrict__ xr,
    const float* __restrict__ br)
{
    __shared__ float2 pse[8][HEADS][CAP];   // per-head (src_as_float, exp_logit)

    int warp = (blockIdx.x * blockDim.x + threadIdx.x) >> 5;
    int wip  = threadIdx.x >> 5;
    int lane = threadIdx.x & 31;
    if (warp >= NN) return;
    int n = warp;
    int begin = g_offs[n], end = g_offs[n + 1];
    int deg = end - begin;
    if (LAYER == 2 && lane == 0) g_deg[n] = 0;   // reset for next replay

    float4 sdv = *(const float4*)&sd[n * HEADS];
    float4 ssn = *(const float4*)&ss[n * HEADS];
    // softmax shift-invariance: logits are O(1), exp never overflows
    float es0 = __expf(lrelu(ssn.x + sdv.x));
    float es1 = __expf(lrelu(ssn.y + sdv.y));
    float es2 = __expf(lrelu(ssn.z + sdv.z));
    float es3 = __expf(lrelu(ssn.w + sdv.w));
    float d0 = 0.f, d1 = 0.f, d2 = 0.f, d3 = 0.f;

    int hd = lane >> 3;
    int c0 = lane * 4;

    if (deg <= CAP) {
        for (int i = lane; i < deg; i += 32) {
            int s = g_sorted_src[begin + i];
            float4 sv = *(const float4*)&ss[s * HEADS];
            float fs = __int_as_float(s);
            float e0 = __expf(lrelu(sv.x + sdv.x));
            float e1 = __expf(lrelu(sv.y + sdv.y));
            float e2 = __expf(lrelu(sv.z + sdv.z));
            float e3 = __expf(lrelu(sv.w + sdv.w));
            pse[wip][0][i] = make_float2(fs, e0);
            pse[wip][1][i] = make_float2(fs, e1);
            pse[wip][2][i] = make_float2(fs, e2);
            pse[wip][3][i] = make_float2(fs, e3);
            d0 += e0; d1 += e1; d2 += e2; d3 += e3;
        }
#pragma unroll
        for (int off = 16; off; off >>= 1) {
            d0 += __shfl_xor_sync(0xffffffffu, d0, off);
            d1 += __shfl_xor_sync(0xffffffffu, d1, off);
            d2 += __shfl_xor_sync(0xffffffffu, d2, off);
            d3 += __shfl_xor_sync(0xffffffffu, d3, off);
        }
        d0 += es0; d1 += es1; d2 += es2; d3 += es3;
        __syncwarp();

        float dh  = (hd == 0) ? d0 : (hd == 1) ? d1 : (hd == 2) ? d2 : d3;
        float esh = (hd == 0) ? es0 : (hd == 1) ? es1 : (hd == 2) ? es2 : es3;
        float inv_dh = 1.f / dh;

        float4 hn = *(const float4*)&h[(long long)n * D + c0];
        float ax = esh * hn.x, ay = esh * hn.y, az = esh * hn.z, aw = esh * hn.w;

        const float2* __restrict__ pp = &pse[wip][hd][0];
#pragma unroll 4
        for (int i = 0; i < deg; ++i) {
            float2 p = pp[i];
            int s = __float_as_int(p.x);
            float e = p.y;
            float4 hv = *(const float4*)&h[(long long)s * D + c0];
            ax += e * hv.x; ay += e * hv.y; az += e * hv.z; aw += e * hv.w;
        }
        ax *= inv_dh; ay *= inv_dh; az *= inv_dh; aw *= inv_dh;

        float4 b = *(const float4*)&bias[c0];
        if (LAYER == 1) {
            float4 o = make_float4(fmaxf(ax + b.x, 0.f), fmaxf(ay + b.y, 0.f),
                                   fmaxf(az + b.z, 0.f), fmaxf(aw + b.w, 0.f));
            *(float4*)&out[(long long)n * D + c0] = o;
        } else {
            float4 r  = *(const float4*)&xr[(long long)n * D + c0];
            float4 bb = *(const float4*)&br[c0];
            float4 o = make_float4(ax + b.x + r.x + bb.x, ay + b.y + r.y + bb.y,
                                   az + b.z + r.z + bb.z, aw + b.w + r.w + bb.w);
            *(float4*)&out[(long long)n * D + c0] = o;
        }
        return;
    }

    // ---- fallback (deg > CAP; statistically unreachable) --------------------------
    for (int e = begin + lane; e < end; e += 32) {
        int s = g_sorted_src[e];
        float4 sv = *(const float4*)&ss[s * HEADS];
        d0 += __expf(lrelu(sv.x + sdv.x));
        d1 += __expf(lrelu(sv.y + sdv.y));
        d2 += __expf(lrelu(sv.z + sdv.z));
        d3 += __expf(lrelu(sv.w + sdv.w));
    }
#pragma unroll
    for (int off = 16; off; off >>= 1) {
        d0 += __shfl_xor_sync(0xffffffffu, d0, off);
        d1 += __shfl_xor_sync(0xffffffffu, d1, off);
        d2 += __shfl_xor_sync(0xffffffffu, d2, off);
        d3 += __shfl_xor_sync(0xffffffffu, d3, off);
    }
    d0 += es0; d1 += es1; d2 += es2; d3 += es3;

    float dh  = (hd == 0) ? d0 : (hd == 1) ? d1 : (hd == 2) ? d2 : d3;
    float esh = (hd == 0) ? es0 : (hd == 1) ? es1 : (hd == 2) ? es2 : es3;
    float sdh = (hd == 0) ? sdv.x : (hd == 1) ? sdv.y : (hd == 2) ? sdv.z : sdv.w;
    float inv_dh = 1.f / dh;

    float4 hn = *(const float4*)&h[(long long)n * D + c0];
    float ax = esh * hn.x, ay = esh * hn.y, az = esh * hn.z, aw = esh * hn.w;
    for (int e = begin; e < end; ++e) {
        int s = g_sorted_src[e];
        float w = __expf(lrelu(ss[s * HEADS + hd] + sdh));
        float4 hv = *(const float4*)&h[(long long)s * D + c0];
        ax += w * hv.x; ay += w * hv.y; az += w * hv.z; aw += w * hv.w;
    }
    ax *= inv_dh; ay *= inv_dh; az *= inv_dh; aw *= inv_dh;

    float4 b = *(const float4*)&bias[c0];
    if (LAYER == 1) {
        float4 o = make_float4(fmaxf(ax + b.x, 0.f), fmaxf(ay + b.y, 0.f),
                               fmaxf(az + b.z, 0.f), fmaxf(aw + b.w, 0.f));
        *(float4*)&out[(long long)n * D + c0] = o;
    } else {
        float4 r  = *(const float4*)&xr[(long long)n * D + c0];
        float4 bb = *(const float4*)&br[c0];
        float4 o = make_float4(ax + b.x + r.x + bb.x, ay + b.y + r.y + bb.y,
                               az + b.z + r.z + bb.z, aw + b.w + r.w + bb.w);
        *(float4*)&out[(long long)n * D + c0] = o;
    }
}

// ---------------- launch ----------------------------------------------------------
extern "C" void kernel_launch(void* const* d_in, const int* in_sizes, int n_in,
                              void* d_out, int out_size) {
    const float* x   = (const float*)d_in[0];
    const void*  ei  = d_in[1];
    const float* W1  = (const float*)d_in[2];
    const float* a1s = (const float*)d_in[3];
    const float* a1d = (const float*)d_in[4];
    const float* b1  = (const float*)d_in[5];
    const float* W2  = (const float*)d_in[6];
    const float* a2s = (const float*)d_in[7];
    const float* a2d = (const float*)d_in[8];
    const float* b2  = (const float*)d_in[9];
    const float* Wr  = (const float*)d_in[10];
    const float* br  = (const float*)d_in[11];
    float* out = (float*)d_out;

    float* bufA; cudaGetSymbolAddress((void**)&bufA, g_bufA);
    float* bufB; cudaGetSymbolAddress((void**)&bufB, g_bufB);
    float* xr;   cudaGetSymbolAddress((void**)&xr, g_xr);
    float* ssp;  cudaGetSymbolAddress((void**)&ssp, g_ss);
    float* sdp;  cudaGetSymbolAddress((void**)&sdp, g_sd);

    // preprocessing: compact counting sort (g_deg zeroed statically / by agg2)
    count_kernel<<<(EE + 255) / 256, 256>>>(ei);
    scan_k1<<<NB_SCAN, 256>>>();
    scan_k2<<<1, 128>>>();
    scan_k3<<<NB_SCAN, 256>>>();
    scatter_kernel<<<(EE + 255) / 256, 256>>>(ei);

    dim3 ggrid((NN + 127) / 128, 2);
    // layer-1 transform + fused scores
    gemm_tc_kernel<true><<<ggrid, 256>>>(x, W1, a1s, a1d, bufA, ssp, sdp);
    // residual transform
    gemm_tc_kernel<false><<<ggrid, 256>>>(x, Wr, nullptr, nullptr, xr, nullptr, nullptr);
    // layer-1 aggregation
    agg_kernel<1><<<(NN + 7) / 8, 256>>>(bufA, ssp, sdp, b1, bufB, nullptr, nullptr);
    // layer-2 transform + fused scores
    gemm_tc_kernel<true><<<ggrid, 256>>>(bufB, W2, a2s, a2d, bufA, ssp, sdp);
    // layer-2 aggregation + residual (+ deg reset)
    agg_kernel<2><<<(NN + 7) / 8, 256>>>(bufA, ssp, sdp, b2, out, xr, br);
}

// round 7
// speedup vs baseline: 1.1123x; 1.1123x over previous
#include <cuda_runtime.h>
#include <cuda_bf16.h>
#include <math.h>
#include <stdint.h>

#define NN 100000
#define EE 1600000
#define D  128
#define HEADS 4
#define CH 32
#define NEG_SLOPE 0.2f
#define CAP 64                         // deg ~ Poisson(16); P(deg>64) ~ 2e-22
#define NB_SCAN ((NN + 1023) / 1024)   // 98

// ---------------- scratch ------------------------------------------------------
__device__ float g_bufA[NN * D];
__device__ float g_bufB[NN * D];
__device__ float g_xr[NN * D];
__device__ float g_ss[NN * HEADS];
__device__ float g_sd[NN * HEADS];
__device__ int   g_deg[NN];            // statically zero; agg2 re-zeroes each launch
__device__ int   g_offs[NN + 1];
__device__ int   g_cursor[NN];
__device__ int   g_sorted_src[EE];
__device__ int   g_bsum[NB_SCAN];

// ---------------- edge dtype detection (per-block inline) -----------------------
__device__ __forceinline__ int detect_s64(const void* ei, int* smem_flag) {
    if (threadIdx.x == 0) *smem_flag = 1;
    __syncthreads();
    if (threadIdx.x < 256)
        if (((const unsigned int*)ei)[2 * threadIdx.x + 1] != 0u) *smem_flag = 0;
    __syncthreads();
    return *smem_flag;
}

// ---------------- counting sort --------------------------------------------------
__global__ void __launch_bounds__(256) count_kernel(const void* __restrict__ ei) {
    __shared__ int s64s;
    int s64 = detect_s64(ei, &s64s);
    int i = blockIdx.x * blockDim.x + threadIdx.x;
    if (i >= EE) return;
    int d = s64 ? (int)((const long long*)ei)[(long long)EE + i]
                : ((const int*)ei)[EE + i];
    atomicAdd(&g_deg[d], 1);
}

__global__ void __launch_bounds__(256) scan_k1() {
    __shared__ int sm[256];
    int b = blockIdx.x, tid = threadIdx.x;
    int base = b * 1024 + tid * 4;
    int s = 0;
#pragma unroll
    for (int j = 0; j < 4; ++j) {
        int idx = base + j;
        if (idx < NN) s += g_deg[idx];
    }
    sm[tid] = s;
    __syncthreads();
    for (int off = 128; off; off >>= 1) {
        if (tid < off) sm[tid] += sm[tid + off];
        __syncthreads();
    }
    if (tid == 0) g_bsum[b] = sm[0];
}

// scan_k3m: per-block scan with INLINE scan of the 98 block sums (k2 merged in)
__global__ void __launch_bounds__(256) scan_k3m() {
    __shared__ int bs[128];
    __shared__ int sm[256];
    int b = blockIdx.x, tid = threadIdx.x;
    if (tid < 128) bs[tid] = (tid < NB_SCAN) ? g_bsum[tid] : 0;
    __syncthreads();
    for (int off = 1; off < 128; off <<= 1) {
        int v = (tid >= off && tid < 128) ? bs[tid - off] : 0;
        __syncthreads();
        if (tid < 128) bs[tid] += v;
        __syncthreads();
    }
    int blockpre = (b == 0) ? 0 : bs[b - 1];

    int base = b * 1024 + tid * 4;
    int v[4];
#pragma unroll
    for (int j = 0; j < 4; ++j) {
        int idx = base + j;
        v[j] = (idx < NN) ? g_deg[idx] : 0;
    }
    int tot = v[0] + v[1] + v[2] + v[3];
    sm[tid] = tot;
    __syncthreads();
    for (int off = 1; off < 256; off <<= 1) {
        int x = (tid >= off) ? sm[tid - off] : 0;
        __syncthreads();
        sm[tid] += x;
        __syncthreads();
    }
    int run = blockpre + ((tid == 0) ? 0 : sm[tid - 1]);
#pragma unroll
    for (int j = 0; j < 4; ++j) {
        int idx = base + j;
        if (idx < NN) {
            g_offs[idx]   = run;
            g_cursor[idx] = run;
            run += v[j];
        }
    }
    if (b == 0 && tid == 0) g_offs[NN] = EE;
}

__global__ void __launch_bounds__(256) scatter_kernel(const void* __restrict__ ei) {
    __shared__ int s64s;
    int s64 = detect_s64(ei, &s64s);
    int i = blockIdx.x * blockDim.x + threadIdx.x;
    if (i >= EE) return;
    int s, d;
    if (s64) {
        s = (int)((const long long*)ei)[i];
        d = (int)((const long long*)ei)[(long long)EE + i];
    } else {
        s = ((const int*)ei)[i];
        d = ((const int*)ei)[EE + i];
    }
    int pos = atomicAdd(&g_cursor[d], 1);
    g_sorted_src[pos] = s;
}

// ---------------- tf32 tensor-core GEMM: 2-stage cp.async pipeline ---------------
__device__ __forceinline__ uint32_t to_tf32u(float x) {
    uint32_t u;
    asm("cvt.rna.tf32.f32 %0, %1;" : "=r"(u) : "f"(x));
    return u;
}

__device__ __forceinline__ void cp16(uint32_t smem_dst, const void* gsrc) {
    asm volatile("cp.async.cg.shared.global [%0], [%1], 16;\n"
                 :: "r"(smem_dst), "l"(gsrc));
}
#define CP_COMMIT()  asm volatile("cp.async.commit_group;\n" ::: "memory")
#define CP_WAIT_1()  asm volatile("cp.async.wait_group 1;\n" ::: "memory")
#define CP_WAIT_0()  asm volatile("cp.async.wait_group 0;\n" ::: "memory")

#define MMA_TF32(c, av, bv)                                                  \
    asm volatile(                                                            \
        "mma.sync.aligned.m16n8k8.row.col.f32.tf32.tf32.f32 "                \
        "{%0,%1,%2,%3},{%4,%5,%6,%7},{%8,%9},{%0,%1,%2,%3};"                 \
        : "+f"((c)[0]), "+f"((c)[1]), "+f"((c)[2]), "+f"((c)[3])             \
        : "r"((av)[0]), "r"((av)[1]), "r"((av)[2]), "r"((av)[3]),            \
          "r"((bv)[0]), "r"((bv)[1]))

#define KC 16          // k-chunk
#define NCH (D / KC)   // 8 chunks
// A row pitch 20 floats (80B, 16B-aligned, conflict-free); W row pitch 132 floats
// block 128(M) x 128(N), 256 thr = 8 warps as 4(M) x 2(N); warp tile 32x64
template<bool SCORES>
__global__ void __launch_bounds__(256, 2) gemm_tc_kernel(
    const float* __restrict__ A, const float* __restrict__ W,
    const float* __restrict__ a_src, const float* __restrict__ a_dst,
    float* __restrict__ out, float* __restrict__ ssrc, float* __restrict__ sdst)
{
    __shared__ float As[2][128][20];   // [stage][m][k] row-major, pad 16->20
    __shared__ float Ws[2][KC][132];   // [stage][k][n] row-major, pad 128->132

    const int tid  = threadIdx.x;
    const int warp = tid >> 5, lane = tid & 31;
    const int g = lane >> 2, t = lane & 3;
    const int wm = warp >> 1;          // 0..3
    const int wn = warp & 1;           // 0..1
    const int m0 = wm * 32, n0 = wn * 64;
    const int row0 = blockIdx.x * 128;

    const uint32_t as_base = (uint32_t)__cvta_generic_to_shared(&As[0][0][0]);
    const uint32_t ws_base = (uint32_t)__cvta_generic_to_shared(&Ws[0][0][0]);

    float acc[2][8][4];
#pragma unroll
    for (int i = 0; i < 2; ++i)
#pragma unroll
        for (int j = 0; j < 8; ++j)
#pragma unroll
            for (int k = 0; k < 4; ++k) acc[i][j][k] = 0.f;

    // stage loader: A chunk 128 rows x 16 k; W chunk 16 k x 128 n
    auto load_stage = [&](int s, int kc) {
#pragma unroll
        for (int it = 0; it < 2; ++it) {
            int idx = tid + it * 256;          // 0..511
            int r = idx >> 2, q = idx & 3;     // A: row, k-quad
            int row = row0 + r;
            if (row >= NN) row = NN - 1;       // clamp; masked on store
            cp16(as_base + (uint32_t)((s * 128 + r) * 20 + q * 4) * 4u,
                 &A[(long long)row * D + kc + q * 4]);
            int kr = idx >> 5, c4 = idx & 31;  // W: k-row, col-quad
            cp16(ws_base + (uint32_t)((s * KC + kr) * 132 + c4 * 4) * 4u,
                 &W[(kc + kr) * D + c4 * 4]);
        }
    };

    load_stage(0, 0);
    CP_COMMIT();

    for (int c = 0; c < NCH; ++c) {
        const int cur = c & 1;
        if (c + 1 < NCH) {
            load_stage((c + 1) & 1, (c + 1) * KC);
            CP_COMMIT();
            CP_WAIT_1();
        } else {
            CP_WAIT_0();
        }
        __syncthreads();

#pragma unroll
        for (int ks = 0; ks < KC; ks += 8) {
            uint32_t a[2][4], b[8][2];
#pragma unroll
            for (int mt = 0; mt < 2; ++mt) {
                int row = m0 + mt * 16 + g;
                a[mt][0] = to_tf32u(As[cur][row][ks + t]);
                a[mt][1] = to_tf32u(As[cur][row + 8][ks + t]);
                a[mt][2] = to_tf32u(As[cur][row][ks + t + 4]);
                a[mt][3] = to_tf32u(As[cur][row + 8][ks + t + 4]);
            }
#pragma unroll
            for (int nt = 0; nt < 8; ++nt) {
                int nc = n0 + nt * 8 + g;
                b[nt][0] = to_tf32u(Ws[cur][ks + t][nc]);
                b[nt][1] = to_tf32u(Ws[cur][ks + t + 4][nc]);
            }
#pragma unroll
            for (int mt = 0; mt < 2; ++mt)
#pragma unroll
                for (int nt = 0; nt < 8; ++nt)
                    MMA_TF32(acc[mt][nt], a[mt], b[nt]);
        }
        __syncthreads();
    }

    // epilogue: warp covers heads h0 = 2*wn (nt 0..3) and h1 = 2*wn+1 (nt 4..7)
    const int h0 = 2 * wn, h1 = 2 * wn + 1;
    float2 asv[8], adv[8];
    if (SCORES) {
#pragma unroll
        for (int nt = 0; nt < 8; ++nt) {
            int head = (nt < 4) ? h0 : h1;
            int cch  = (nt & 3) * 8 + 2 * t;
            asv[nt] = make_float2(a_src[head * CH + cch], a_src[head * CH + cch + 1]);
            adv[nt] = make_float2(a_dst[head * CH + cch], a_dst[head * CH + cch + 1]);
        }
    }
#pragma unroll
    for (int mt = 0; mt < 2; ++mt) {
        int r_lo = row0 + m0 + mt * 16 + g;
        int r_hi = r_lo + 8;
        float sA_lo = 0.f, dA_lo = 0.f, sA_hi = 0.f, dA_hi = 0.f;
        float sB_lo = 0.f, dB_lo = 0.f, sB_hi = 0.f, dB_hi = 0.f;
#pragma unroll
        for (int nt = 0; nt < 8; ++nt) {
            int col = n0 + nt * 8 + 2 * t;
            if (r_lo < NN)
                *(float2*)&out[(long long)r_lo * D + col] =
                    make_float2(acc[mt][nt][0], acc[mt][nt][1]);
            if (r_hi < NN)
                *(float2*)&out[(long long)r_hi * D + col] =
                    make_float2(acc[mt][nt][2], acc[mt][nt][3]);
            if (SCORES) {
                float su_l = acc[mt][nt][0] * asv[nt].x + acc[mt][nt][1] * asv[nt].y;
                float du_l = acc[mt][nt][0] * adv[nt].x + acc[mt][nt][1] * adv[nt].y;
                float su_h = acc[mt][nt][2] * asv[nt].x + acc[mt][nt][3] * asv[nt].y;
                float du_h = acc[mt][nt][2] * adv[nt].x + acc[mt][nt][3] * adv[nt].y;
                if (nt < 4) { sA_lo += su_l; dA_lo += du_l; sA_hi += su_h; dA_hi += du_h; }
                else        { sB_lo += su_l; dB_lo += du_l; sB_hi += su_h; dB_hi += du_h; }
            }
        }
        if (SCORES) {
#pragma unroll
            for (int off = 1; off <= 2; off <<= 1) {
                sA_lo += __shfl_xor_sync(0xffffffffu, sA_lo, off);
                dA_lo += __shfl_xor_sync(0xffffffffu, dA_lo, off);
                sA_hi += __shfl_xor_sync(0xffffffffu, sA_hi, off);
                dA_hi += __shfl_xor_sync(0xffffffffu, dA_hi, off);
                sB_lo += __shfl_xor_sync(0xffffffffu, sB_lo, off);
                dB_lo += __shfl_xor_sync(0xffffffffu, dB_lo, off);
                sB_hi += __shfl_xor_sync(0xffffffffu, sB_hi, off);
                dB_hi += __shfl_xor_sync(0xffffffffu, dB_hi, off);
            }
            if (t == 0) {
                if (r_lo < NN) {
                    ssrc[r_lo * HEADS + h0] = sA_lo; sdst[r_lo * HEADS + h0] = dA_lo;
                    ssrc[r_lo * HEADS + h1] = sB_lo; sdst[r_lo * HEADS + h1] = dB_lo;
                }
                if (r_hi < NN) {
                    ssrc[r_hi * HEADS + h0] = sA_hi; sdst[r_hi * HEADS + h0] = dA_hi;
                    ssrc[r_hi * HEADS + h1] = sB_hi; sdst[r_hi * HEADS + h1] = dB_hi;
                }
            }
        }
    }
}

// ---------------- softmax + aggregation (no max shift; packed (src,e) planes) ---
__device__ __forceinline__ float lrelu(float v) { return v > 0.f ? v : NEG_SLOPE * v; }

template<int LAYER>
__global__ void __launch_bounds__(256) agg_kernel(
    const float* __restrict__ h,
    const float* __restrict__ ss,
    const float* __restrict__ sd,
    const float* __restrict__ bias,
    float* __restrict__ out,
    const float* __restrict__ xr,
    const float* __restrict__ br)
{
    __shared__ float2 pse[8][HEADS][CAP];   // per-head (src_as_float, exp_logit)

    int warp = (blockIdx.x * blockDim.x + threadIdx.x) >> 5;
    int wip  = threadIdx.x >> 5;
    int lane = threadIdx.x & 31;
    if (warp >= NN) return;
    int n = warp;
    int begin = g_offs[n], end = g_offs[n + 1];
    int deg = end - begin;
    if (LAYER == 2 && lane == 0) g_deg[n] = 0;   // reset for next replay

    float4 sdv = *(const float4*)&sd[n * HEADS];
    float4 ssn = *(const float4*)&ss[n * HEADS];
    // softmax shift-invariance: logits are O(1), exp never overflows
    float es0 = __expf(lrelu(ssn.x + sdv.x));
    float es1 = __expf(lrelu(ssn.y + sdv.y));
    float es2 = __expf(lrelu(ssn.z + sdv.z));
    float es3 = __expf(lrelu(ssn.w + sdv.w));
    float d0 = 0.f, d1 = 0.f, d2 = 0.f, d3 = 0.f;

    int hd = lane >> 3;
    int c0 = lane * 4;

    if (deg <= CAP) {
        for (int i = lane; i < deg; i += 32) {
            int s = g_sorted_src[begin + i];
            float4 sv = *(const float4*)&ss[s * HEADS];
            float fs = __int_as_float(s);
            float e0 = __expf(lrelu(sv.x + sdv.x));
            float e1 = __expf(lrelu(sv.y + sdv.y));
            float e2 = __expf(lrelu(sv.z + sdv.z));
            float e3 = __expf(lrelu(sv.w + sdv.w));
            pse[wip][0][i] = make_float2(fs, e0);
            pse[wip][1][i] = make_float2(fs, e1);
            pse[wip][2][i] = make_float2(fs, e2);
            pse[wip][3][i] = make_float2(fs, e3);
            d0 += e0; d1 += e1; d2 += e2; d3 += e3;
        }
#pragma unroll
        for (int off = 16; off; off >>= 1) {
            d0 += __shfl_xor_sync(0xffffffffu, d0, off);
            d1 += __shfl_xor_sync(0xffffffffu, d1, off);
            d2 += __shfl_xor_sync(0xffffffffu, d2, off);
            d3 += __shfl_xor_sync(0xffffffffu, d3, off);
        }
        d0 += es0; d1 += es1; d2 += es2; d3 += es3;
        __syncwarp();

        float dh  = (hd == 0) ? d0 : (hd == 1) ? d1 : (hd == 2) ? d2 : d3;
        float esh = (hd == 0) ? es0 : (hd == 1) ? es1 : (hd == 2) ? es2 : es3;
        float inv_dh = 1.f / dh;

        float4 hn = *(const float4*)&h[(long long)n * D + c0];
        float ax = esh * hn.x, ay = esh * hn.y, az = esh * hn.z, aw = esh * hn.w;

        const float2* __restrict__ pp = &pse[wip][hd][0];
#pragma unroll 8
        for (int i = 0; i < deg; ++i) {
            float2 p = pp[i];
            int s = __float_as_int(p.x);
            float e = p.y;
            float4 hv = *(const float4*)&h[(long long)s * D + c0];
            ax += e * hv.x; ay += e * hv.y; az += e * hv.z; aw += e * hv.w;
        }
        ax *= inv_dh; ay *= inv_dh; az *= inv_dh; aw *= inv_dh;

        float4 b = *(const float4*)&bias[c0];
        if (LAYER == 1) {
            float4 o = make_float4(fmaxf(ax + b.x, 0.f), fmaxf(ay + b.y, 0.f),
                                   fmaxf(az + b.z, 0.f), fmaxf(aw + b.w, 0.f));
            *(float4*)&out[(long long)n * D + c0] = o;
        } else {
            float4 r  = *(const float4*)&xr[(long long)n * D + c0];
            float4 bb = *(const float4*)&br[c0];
            float4 o = make_float4(ax + b.x + r.x + bb.x, ay + b.y + r.y + bb.y,
                                   az + b.z + r.z + bb.z, aw + b.w + r.w + bb.w);
            *(float4*)&out[(long long)n * D + c0] = o;
        }
        return;
    }

    // ---- fallback (deg > CAP; statistically unreachable) --------------------------
    for (int e = begin + lane; e < end; e += 32) {
        int s = g_sorted_src[e];
        float4 sv = *(const float4*)&ss[s * HEADS];
        d0 += __expf(lrelu(sv.x + sdv.x));
        d1 += __expf(lrelu(sv.y + sdv.y));
        d2 += __expf(lrelu(sv.z + sdv.z));
        d3 += __expf(lrelu(sv.w + sdv.w));
    }
#pragma unroll
    for (int off = 16; off; off >>= 1) {
        d0 += __shfl_xor_sync(0xffffffffu, d0, off);
        d1 += __shfl_xor_sync(0xffffffffu, d1, off);
        d2 += __shfl_xor_sync(0xffffffffu, d2, off);
        d3 += __shfl_xor_sync(0xffffffffu, d3, off);
    }
    d0 += es0; d1 += es1; d2 += es2; d3 += es3;

    float dh  = (hd == 0) ? d0 : (hd == 1) ? d1 : (hd == 2) ? d2 : d3;
    float esh = (hd == 0) ? es0 : (hd == 1) ? es1 : (hd == 2) ? es2 : es3;
    float sdh = (hd == 0) ? sdv.x : (hd == 1) ? sdv.y : (hd == 2) ? sdv.z : sdv.w;
    float inv_dh = 1.f / dh;

    float4 hn = *(const float4*)&h[(long long)n * D + c0];
    float ax = esh * hn.x, ay = esh * hn.y, az = esh * hn.z, aw = esh * hn.w;
    for (int e = begin; e < end; ++e) {
        int s = g_sorted_src[e];
        float w = __expf(lrelu(ss[s * HEADS + hd] + sdh));
        float4 hv = *(const float4*)&h[(long long)s * D + c0];
        ax += w * hv.x; ay += w * hv.y; az += w * hv.z; aw += w * hv.w;
    }
    ax *= inv_dh; ay *= inv_dh; az *= inv_dh; aw *= inv_dh;

    float4 b = *(const float4*)&bias[c0];
    if (LAYER == 1) {
        float4 o = make_float4(fmaxf(ax + b.x, 0.f), fmaxf(ay + b.y, 0.f),
                               fmaxf(az + b.z, 0.f), fmaxf(aw + b.w, 0.f));
        *(float4*)&out[(long long)n * D + c0] = o;
    } else {
        float4 r  = *(const float4*)&xr[(long long)n * D + c0];
        float4 bb = *(const float4*)&br[c0];
        float4 o = make_float4(ax + b.x + r.x + bb.x, ay + b.y + r.y + bb.y,
                               az + b.z + r.z + bb.z, aw + b.w + r.w + bb.w);
        *(float4*)&out[(long long)n * D + c0] = o;
    }
}

// ---------------- launch ----------------------------------------------------------
extern "C" void kernel_launch(void* const* d_in, const int* in_sizes, int n_in,
                              void* d_out, int out_size) {
    const float* x   = (const float*)d_in[0];
    const void*  ei  = d_in[1];
    const float* W1  = (const float*)d_in[2];
    const float* a1s = (const float*)d_in[3];
    const float* a1d = (const float*)d_in[4];
    const float* b1  = (const float*)d_in[5];
    const float* W2  = (const float*)d_in[6];
    const float* a2s = (const float*)d_in[7];
    const float* a2d = (const float*)d_in[8];
    const float* b2  = (const float*)d_in[9];
    const float* Wr  = (const float*)d_in[10];
    const float* br  = (const float*)d_in[11];
    float* out = (float*)d_out;

    float* bufA; cudaGetSymbolAddress((void**)&bufA, g_bufA);
    float* bufB; cudaGetSymbolAddress((void**)&bufB, g_bufB);
    float* xr;   cudaGetSymbolAddress((void**)&xr, g_xr);
    float* ssp;  cudaGetSymbolAddress((void**)&ssp, g_ss);
    float* sdp;  cudaGetSymbolAddress((void**)&sdp, g_sd);

    const int ggrid = (NN + 127) / 128;

    // interleave independent preproc + GEMMs (slot 4 profiles the new GEMM)
    count_kernel<<<(EE + 255) / 256, 256>>>(ei);                              // 1
    gemm_tc_kernel<true><<<ggrid, 256>>>(x, W1, a1s, a1d, bufA, ssp, sdp);    // 2
    scan_k1<<<NB_SCAN, 256>>>();                                              // 3
    gemm_tc_kernel<false><<<ggrid, 256>>>(x, Wr, nullptr, nullptr,
                                          xr, nullptr, nullptr);              // 4 <- profiled
    scan_k3m<<<NB_SCAN, 256>>>();                                             // 5
    scatter_kernel<<<(EE + 255) / 256, 256>>>(ei);                            // 6
    agg_kernel<1><<<(NN + 7) / 8, 256>>>(bufA, ssp, sdp, b1, bufB,
                                         nullptr, nullptr);                   // 7
    gemm_tc_kernel<true><<<ggrid, 256>>>(bufB, W2, a2s, a2d, bufA, ssp, sdp); // 8
    agg_kernel<2><<<(NN + 7) / 8, 256>>>(bufA, ssp, sdp, b2, out, xr, br);    // 9
}

// round 8
// speedup vs baseline: 1.1256x; 1.0120x over previous
#include <cuda_runtime.h>
#include <cuda_bf16.h>
#include <math.h>
#include <stdint.h>

#define NN 100000
#define EE 1600000
#define D  128
#define HEADS 4
#define CH 32
#define NEG_SLOPE 0.2f
#define CAP 64                         // deg ~ Poisson(16); P(deg>64) ~ 2e-22
#define NB_SCAN ((NN + 1023) / 1024)   // 98 blocks (single wave; < 148 SMs)

// ---------------- scratch ------------------------------------------------------
__device__ float g_bufA[NN * D];
__device__ float g_bufB[NN * D];
__device__ float g_xr[NN * D];
__device__ __nv_bfloat16 g_hb[NN * D];   // bf16 copy of current layer's h (gather)
__device__ float g_ss[NN * HEADS];
__device__ float g_sd[NN * HEADS];
__device__ int   g_deg[NN];
__device__ int   g_offs[NN + 1];
__device__ int   g_cursor[NN];
__device__ int   g_sorted_src[EE];
__device__ int   g_bsum[NB_SCAN];
// grid barrier (gen monotonic across graph replays; count self-resets)
__device__ unsigned g_bar_count = 0;
__device__ volatile unsigned g_bar_gen = 0;

__device__ __forceinline__ void gbar_scan() {
    __syncthreads();
    if (threadIdx.x == 0) {
        __threadfence();
        unsigned gen = g_bar_gen;
        if (atomicAdd(&g_bar_count, 1u) == NB_SCAN - 1) {
            g_bar_count = 0;
            __threadfence();
            g_bar_gen = gen + 1;
        } else {
            while (g_bar_gen == gen) { }
        }
        __threadfence();
    }
    __syncthreads();
}

// ---------------- edge dtype detection (per-block inline) -----------------------
__device__ __forceinline__ int detect_s64(const void* ei, int* smem_flag) {
    if (threadIdx.x == 0) *smem_flag = 1;
    __syncthreads();
    if (threadIdx.x < 256)
        if (((const unsigned int*)ei)[2 * threadIdx.x + 1] != 0u) *smem_flag = 0;
    __syncthreads();
    return *smem_flag;
}

// ---------------- counting sort --------------------------------------------------
__global__ void __launch_bounds__(256) count_kernel(const void* __restrict__ ei) {
    __shared__ int s64s;
    int s64 = detect_s64(ei, &s64s);
    int i = blockIdx.x * blockDim.x + threadIdx.x;
    if (i >= EE) return;
    int d = s64 ? (int)((const long long*)ei)[(long long)EE + i]
                : ((const int*)ei)[EE + i];
    atomicAdd(&g_deg[d], 1);
}

// fused scan: block reduce -> grid barrier -> per-block prefix + offsets
__global__ void __launch_bounds__(256) scan_fused() {
    __shared__ int sm[256];
    __shared__ int blockpre;
    int b = blockIdx.x, tid = threadIdx.x;
    int base = b * 1024 + tid * 4;

    int v[4];
#pragma unroll
    for (int j = 0; j < 4; ++j) {
        int idx = base + j;
        v[j] = (idx < NN) ? g_deg[idx] : 0;
    }
    int tot = v[0] + v[1] + v[2] + v[3];

    // phase A: block total
    sm[tid] = tot;
    __syncthreads();
    for (int off = 128; off; off >>= 1) {
        if (tid < off) sm[tid] += sm[tid + off];
        __syncthreads();
    }
    if (tid == 0) g_bsum[b] = sm[0];

    gbar_scan();

    // phase B: block prefix (thread 0 serial over 98) + in-block scan
    if (tid == 0) {
        int p = 0;
        for (int i = 0; i < b; ++i) p += g_bsum[i];
        blockpre = p;
    }
    sm[tid] = tot;
    __syncthreads();
    for (int off = 1; off < 256; off <<= 1) {
        int x = (tid >= off) ? sm[tid - off] : 0;
        __syncthreads();
        sm[tid] += x;
        __syncthreads();
    }
    int run = blockpre + ((tid == 0) ? 0 : sm[tid - 1]);
#pragma unroll
    for (int j = 0; j < 4; ++j) {
        int idx = base + j;
        if (idx < NN) {
            g_offs[idx]   = run;
            g_cursor[idx] = run;
            run += v[j];
        }
    }
    if (b == 0 && tid == 0) g_offs[NN] = EE;
}

__global__ void __launch_bounds__(256) scatter_kernel(const void* __restrict__ ei) {
    __shared__ int s64s;
    int s64 = detect_s64(ei, &s64s);
    int i = blockIdx.x * blockDim.x + threadIdx.x;
    if (i >= EE) return;
    int s, d;
    if (s64) {
        s = (int)((const long long*)ei)[i];
        d = (int)((const long long*)ei)[(long long)EE + i];
    } else {
        s = ((const int*)ei)[i];
        d = ((const int*)ei)[EE + i];
    }
    int pos = atomicAdd(&g_cursor[d], 1);
    g_sorted_src[pos] = s;
}

// ---------------- tf32 tensor-core GEMM: 2-stage cp.async pipeline ---------------
__device__ __forceinline__ uint32_t to_tf32u(float x) {
    uint32_t u;
    asm("cvt.rna.tf32.f32 %0, %1;" : "=r"(u) : "f"(x));
    return u;
}

__device__ __forceinline__ void cp16(uint32_t smem_dst, const void* gsrc) {
    asm volatile("cp.async.cg.shared.global [%0], [%1], 16;\n"
                 :: "r"(smem_dst), "l"(gsrc));
}
#define CP_COMMIT()  asm volatile("cp.async.commit_group;\n" ::: "memory")
#define CP_WAIT_1()  asm volatile("cp.async.wait_group 1;\n" ::: "memory")
#define CP_WAIT_0()  asm volatile("cp.async.wait_group 0;\n" ::: "memory")

#define MMA_TF32(c, av, bv)                                                  \
    asm volatile(                                                            \
        "mma.sync.aligned.m16n8k8.row.col.f32.tf32.tf32.f32 "                \
        "{%0,%1,%2,%3},{%4,%5,%6,%7},{%8,%9},{%0,%1,%2,%3};"                 \
        : "+f"((c)[0]), "+f"((c)[1]), "+f"((c)[2]), "+f"((c)[3])             \
        : "r"((av)[0]), "r"((av)[1]), "r"((av)[2]), "r"((av)[3]),            \
          "r"((bv)[0]), "r"((bv)[1]))

#define KC 16
#define NCH (D / KC)
// block 128(M) x 128(N), 256 thr = 8 warps as 4(M) x 2(N); warp tile 32x64
template<bool SCORES, bool HBOUT>
__global__ void __launch_bounds__(256, 2) gemm_tc_kernel(
    const float* __restrict__ A, const float* __restrict__ W,
    const float* __restrict__ a_src, const float* __restrict__ a_dst,
    float* __restrict__ out, __nv_bfloat16* __restrict__ hb,
    float* __restrict__ ssrc, float* __restrict__ sdst)
{
    __shared__ float As[2][128][20];
    __shared__ float Ws[2][KC][132];

    const int tid  = threadIdx.x;
    const int warp = tid >> 5, lane = tid & 31;
    const int g = lane >> 2, t = lane & 3;
    const int wm = warp >> 1;
    const int wn = warp & 1;
    const int m0 = wm * 32, n0 = wn * 64;
    const int row0 = blockIdx.x * 128;

    const uint32_t as_base = (uint32_t)__cvta_generic_to_shared(&As[0][0][0]);
    const uint32_t ws_base = (uint32_t)__cvta_generic_to_shared(&Ws[0][0][0]);

    float acc[2][8][4];
#pragma unroll
    for (int i = 0; i < 2; ++i)
#pragma unroll
        for (int j = 0; j < 8; ++j)
#pragma unroll
            for (int k = 0; k < 4; ++k) acc[i][j][k] = 0.f;

    auto load_stage = [&](int s, int kc) {
#pragma unroll
        for (int it = 0; it < 2; ++it) {
            int idx = tid + it * 256;
            int r = idx >> 2, q = idx & 3;
            int row = row0 + r;
            if (row >= NN) row = NN - 1;
            cp16(as_base + (uint32_t)((s * 128 + r) * 20 + q * 4) * 4u,
                 &A[(long long)row * D + kc + q * 4]);
            int kr = idx >> 5, c4 = idx & 31;
            cp16(ws_base + (uint32_t)((s * KC + kr) * 132 + c4 * 4) * 4u,
                 &W[(kc + kr) * D + c4 * 4]);
        }
    };

    load_stage(0, 0);
    CP_COMMIT();

    for (int c = 0; c < NCH; ++c) {
        const int cur = c & 1;
        if (c + 1 < NCH) {
            load_stage((c + 1) & 1, (c + 1) * KC);
            CP_COMMIT();
            CP_WAIT_1();
        } else {
            CP_WAIT_0();
        }
        __syncthreads();

#pragma unroll
        for (int ks = 0; ks < KC; ks += 8) {
            uint32_t a[2][4], b[8][2];
#pragma unroll
            for (int mt = 0; mt < 2; ++mt) {
                int row = m0 + mt * 16 + g;
                a[mt][0] = to_tf32u(As[cur][row][ks + t]);
                a[mt][1] = to_tf32u(As[cur][row + 8][ks + t]);
                a[mt][2] = to_tf32u(As[cur][row][ks + t + 4]);
                a[mt][3] = to_tf32u(As[cur][row + 8][ks + t + 4]);
            }
#pragma unroll
            for (int nt = 0; nt < 8; ++nt) {
                int nc = n0 + nt * 8 + g;
                b[nt][0] = to_tf32u(Ws[cur][ks + t][nc]);
                b[nt][1] = to_tf32u(Ws[cur][ks + t + 4][nc]);
            }
#pragma unroll
            for (int mt = 0; mt < 2; ++mt)
#pragma unroll
                for (int nt = 0; nt < 8; ++nt)
                    MMA_TF32(acc[mt][nt], a[mt], b[nt]);
        }
        __syncthreads();
    }

    const int h0 = 2 * wn, h1 = 2 * wn + 1;
    float2 asv[8], adv[8];
    if (SCORES) {
#pragma unroll
        for (int nt = 0; nt < 8; ++nt) {
            int head = (nt < 4) ? h0 : h1;
            int cch  = (nt & 3) * 8 + 2 * t;
            asv[nt] = make_float2(a_src[head * CH + cch], a_src[head * CH + cch + 1]);
            adv[nt] = make_float2(a_dst[head * CH + cch], a_dst[head * CH + cch + 1]);
        }
    }
#pragma unroll
    for (int mt = 0; mt < 2; ++mt) {
        int r_lo = row0 + m0 + mt * 16 + g;
        int r_hi = r_lo + 8;
        float sA_lo = 0.f, dA_lo = 0.f, sA_hi = 0.f, dA_hi = 0.f;
        float sB_lo = 0.f, dB_lo = 0.f, sB_hi = 0.f, dB_hi = 0.f;
#pragma unroll
        for (int nt = 0; nt < 8; ++nt) {
            int col = n0 + nt * 8 + 2 * t;
            if (r_lo < NN) {
                float2 v = make_float2(acc[mt][nt][0], acc[mt][nt][1]);
                *(float2*)&out[(long long)r_lo * D + col] = v;
                if (HBOUT)
                    *(__nv_bfloat162*)&hb[(long long)r_lo * D + col] =
                        __float22bfloat162_rn(v);
            }
            if (r_hi < NN) {
                float2 v = make_float2(acc[mt][nt][2], acc[mt][nt][3]);
                *(float2*)&out[(long long)r_hi * D + col] = v;
                if (HBOUT)
                    *(__nv_bfloat162*)&hb[(long long)r_hi * D + col] =
                        __float22bfloat162_rn(v);
            }
            if (SCORES) {
                float su_l = acc[mt][nt][0] * asv[nt].x + acc[mt][nt][1] * asv[nt].y;
                float du_l = acc[mt][nt][0] * adv[nt].x + acc[mt][nt][1] * adv[nt].y;
                float su_h = acc[mt][nt][2] * asv[nt].x + acc[mt][nt][3] * asv[nt].y;
                float du_h = acc[mt][nt][2] * adv[nt].x + acc[mt][nt][3] * adv[nt].y;
                if (nt < 4) { sA_lo += su_l; dA_lo += du_l; sA_hi += su_h; dA_hi += du_h; }
                else        { sB_lo += su_l; dB_lo += du_l; sB_hi += su_h; dB_hi += du_h; }
            }
        }
        if (SCORES) {
#pragma unroll
            for (int off = 1; off <= 2; off <<= 1) {
                sA_lo += __shfl_xor_sync(0xffffffffu, sA_lo, off);
                dA_lo += __shfl_xor_sync(0xffffffffu, dA_lo, off);
                sA_hi += __shfl_xor_sync(0xffffffffu, sA_hi, off);
                dA_hi += __shfl_xor_sync(0xffffffffu, dA_hi, off);
                sB_lo += __shfl_xor_sync(0xffffffffu, sB_lo, off);
                dB_lo += __shfl_xor_sync(0xffffffffu, dB_lo, off);
                sB_hi += __shfl_xor_sync(0xffffffffu, sB_hi, off);
                dB_hi += __shfl_xor_sync(0xffffffffu, dB_hi, off);
            }
            if (t == 0) {
                if (r_lo < NN) {
                    ssrc[r_lo * HEADS + h0] = sA_lo; sdst[r_lo * HEADS + h0] = dA_lo;
                    ssrc[r_lo * HEADS + h1] = sB_lo; sdst[r_lo * HEADS + h1] = dB_lo;
                }
                if (r_hi < NN) {
                    ssrc[r_hi * HEADS + h0] = sA_hi; sdst[r_hi * HEADS + h0] = dA_hi;
                    ssrc[r_hi * HEADS + h1] = sB_hi; sdst[r_hi * HEADS + h1] = dB_hi;
                }
            }
        }
    }
}

// ---------------- softmax + aggregation: bf16 gather -----------------------------
__device__ __forceinline__ float lrelu(float v) { return v > 0.f ? v : NEG_SLOPE * v; }

template<int LAYER>
__global__ void __launch_bounds__(256) agg_kernel(
    const __nv_bfloat16* __restrict__ hb,
    const float* __restrict__ ss,
    const float* __restrict__ sd,
    const float* __restrict__ bias,
    float* __restrict__ out,
    const float* __restrict__ xr,
    const float* __restrict__ br)
{
    __shared__ float2 pse[8][HEADS][CAP];   // per-head (src_as_float, exp_logit)

    int warp = (blockIdx.x * blockDim.x + threadIdx.x) >> 5;
    int wip  = threadIdx.x >> 5;
    int lane = threadIdx.x & 31;
    if (warp >= NN) return;
    int n = warp;
    int begin = g_offs[n], end = g_offs[n + 1];
    int deg = end - begin;
    if (LAYER == 2 && lane == 0) g_deg[n] = 0;   // reset for next replay

    float4 sdv = *(const float4*)&sd[n * HEADS];
    float4 ssn = *(const float4*)&ss[n * HEADS];
    float es0 = __expf(lrelu(ssn.x + sdv.x));
    float es1 = __expf(lrelu(ssn.y + sdv.y));
    float es2 = __expf(lrelu(ssn.z + sdv.z));
    float es3 = __expf(lrelu(ssn.w + sdv.w));
    float d0 = 0.f, d1 = 0.f, d2 = 0.f, d3 = 0.f;

    int hd = lane >> 3;
    int c0 = lane * 4;

    auto gather4 = [&](int s, float& vx, float& vy, float& vz, float& vw) {
        uint2 u = *(const uint2*)&hb[(long long)s * D + c0];
        __nv_bfloat162 p0 = *reinterpret_cast<__nv_bfloat162*>(&u.x);
        __nv_bfloat162 p1 = *reinterpret_cast<__nv_bfloat162*>(&u.y);
        float2 f0 = __bfloat1622float2(p0);
        float2 f1 = __bfloat1622float2(p1);
        vx = f0.x; vy = f0.y; vz = f1.x; vw = f1.y;
    };

    if (deg <= CAP) {
        for (int i = lane; i < deg; i += 32) {
            int s = g_sorted_src[begin + i];
            float4 sv = *(const float4*)&ss[s * HEADS];
            float fs = __int_as_float(s);
            float e0 = __expf(lrelu(sv.x + sdv.x));
            float e1 = __expf(lrelu(sv.y + sdv.y));
            float e2 = __expf(lrelu(sv.z + sdv.z));
            float e3 = __expf(lrelu(sv.w + sdv.w));
            pse[wip][0][i] = make_float2(fs, e0);
            pse[wip][1][i] = make_float2(fs, e1);
            pse[wip][2][i] = make_float2(fs, e2);
            pse[wip][3][i] = make_float2(fs, e3);
            d0 += e0; d1 += e1; d2 += e2; d3 += e3;
        }
#pragma unroll
        for (int off = 16; off; off >>= 1) {
            d0 += __shfl_xor_sync(0xffffffffu, d0, off);
            d1 += __shfl_xor_sync(0xffffffffu, d1, off);
            d2 += __shfl_xor_sync(0xffffffffu, d2, off);
            d3 += __shfl_xor_sync(0xffffffffu, d3, off);
        }
        d0 += es0; d1 += es1; d2 += es2; d3 += es3;
        __syncwarp();

        float dh  = (hd == 0) ? d0 : (hd == 1) ? d1 : (hd == 2) ? d2 : d3;
        float esh = (hd == 0) ? es0 : (hd == 1) ? es1 : (hd == 2) ? es2 : es3;
        float inv_dh = 1.f / dh;

        float hx, hy, hz, hw;
        gather4(n, hx, hy, hz, hw);
        float ax = esh * hx, ay = esh * hy, az = esh * hz, aw = esh * hw;

        const float2* __restrict__ pp = &pse[wip][hd][0];
#pragma unroll 8
        for (int i = 0; i < deg; ++i) {
            float2 p = pp[i];
            int s = __float_as_int(p.x);
            float e = p.y;
            float vx, vy, vz, vw;
            gather4(s, vx, vy, vz, vw);
            ax += e * vx; ay += e * vy; az += e * vz; aw += e * vw;
        }
        ax *= inv_dh; ay *= inv_dh; az *= inv_dh; aw *= inv_dh;

        float4 b = *(const float4*)&bias[c0];
        if (LAYER == 1) {
            float4 o = make_float4(fmaxf(ax + b.x, 0.f), fmaxf(ay + b.y, 0.f),
                                   fmaxf(az + b.z, 0.f), fmaxf(aw + b.w, 0.f));
            *(float4*)&out[(long long)n * D + c0] = o;
        } else {
            float4 r  = *(const float4*)&xr[(long long)n * D + c0];
            float4 bb = *(const float4*)&br[c0];
            float4 o = make_float4(ax + b.x + r.x + bb.x, ay + b.y + r.y + bb.y,
                                   az + b.z + r.z + bb.z, aw + b.w + r.w + bb.w);
            *(float4*)&out[(long long)n * D + c0] = o;
        }
        return;
    }

    // ---- fallback (deg > CAP; statistically unreachable) --------------------------
    for (int e = begin + lane; e < end; e += 32) {
        int s = g_sorted_src[e];
        float4 sv = *(const float4*)&ss[s * HEADS];
        d0 += __expf(lrelu(sv.x + sdv.x));
        d1 += __expf(lrelu(sv.y + sdv.y));
        d2 += __expf(lrelu(sv.z + sdv.z));
        d3 += __expf(lrelu(sv.w + sdv.w));
    }
#pragma unroll
    for (int off = 16; off; off >>= 1) {
        d0 += __shfl_xor_sync(0xffffffffu, d0, off);
        d1 += __shfl_xor_sync(0xffffffffu, d1, off);
        d2 += __shfl_xor_sync(0xffffffffu, d2, off);
        d3 += __shfl_xor_sync(0xffffffffu, d3, off);
    }
    d0 += es0; d1 += es1; d2 += es2; d3 += es3;

    float dh  = (hd == 0) ? d0 : (hd == 1) ? d1 : (hd == 2) ? d2 : d3;
    float esh = (hd == 0) ? es0 : (hd == 1) ? es1 : (hd == 2) ? es2 : es3;
    float sdh = (hd == 0) ? sdv.x : (hd == 1) ? sdv.y : (hd == 2) ? sdv.z : sdv.w;
    float inv_dh = 1.f / dh;

    float hx, hy, hz, hw;
    {
        uint2 u = *(const uint2*)&hb[(long long)n * D + c0];
        __nv_bfloat162 p0 = *reinterpret_cast<__nv_bfloat162*>(&u.x);
        __nv_bfloat162 p1 = *reinterpret_cast<__nv_bfloat162*>(&u.y);
        float2 f0 = __bfloat1622float2(p0), f1 = __bfloat1622float2(p1);
        hx = f0.x; hy = f0.y; hz = f1.x; hw = f1.y;
    }
    float ax = esh * hx, ay = esh * hy, az = esh * hz, aw = esh * hw;
    for (int e = begin; e < end; ++e) {
        int s = g_sorted_src[e];
        float w = __expf(lrelu(ss[s * HEADS + hd] + sdh));
        uint2 u = *(const uint2*)&hb[(long long)s * D + c0];
        __nv_bfloat162 p0 = *reinterpret_cast<__nv_bfloat162*>(&u.x);
        __nv_bfloat162 p1 = *reinterpret_cast<__nv_bfloat162*>(&u.y);
        float2 f0 = __bfloat1622float2(p0), f1 = __bfloat1622float2(p1);
        ax += w * f0.x; ay += w * f0.y; az += w * f1.x; aw += w * f1.y;
    }
    ax *= inv_dh; ay *= inv_dh; az *= inv_dh; aw *= inv_dh;

    float4 b = *(const float4*)&bias[c0];
    if (LAYER == 1) {
        float4 o = make_float4(fmaxf(ax + b.x, 0.f), fmaxf(ay + b.y, 0.f),
                               fmaxf(az + b.z, 0.f), fmaxf(aw + b.w, 0.f));
        *(float4*)&out[(long long)n * D + c0] = o;
    } else {
        float4 r  = *(const float4*)&xr[(long long)n * D + c0];
        float4 bb = *(const float4*)&br[c0];
        float4 o = make_float4(ax + b.x + r.x + bb.x, ay + b.y + r.y + bb.y,
                               az + b.z + r.z + bb.z, aw + b.w + r.w + bb.w);
        *(float4*)&out[(long long)n * D + c0] = o;
    }
}

// ---------------- launch ----------------------------------------------------------
extern "C" void kernel_launch(void* const* d_in, const int* in_sizes, int n_in,
                              void* d_out, int out_size) {
    const float* x   = (const float*)d_in[0];
    const void*  ei  = d_in[1];
    const float* W1  = (const float*)d_in[2];
    const float* a1s = (const float*)d_in[3];
    const float* a1d = (const float*)d_in[4];
    const float* b1  = (const float*)d_in[5];
    const float* W2  = (const float*)d_in[6];
    const float* a2s = (const float*)d_in[7];
    const float* a2d = (const float*)d_in[8];
    const float* b2  = (const float*)d_in[9];
    const float* Wr  = (const float*)d_in[10];
    const float* br  = (const float*)d_in[11];
    float* out = (float*)d_out;

    float* bufA; cudaGetSymbolAddress((void**)&bufA, g_bufA);
    float* bufB; cudaGetSymbolAddress((void**)&bufB, g_bufB);
    float* xr;   cudaGetSymbolAddress((void**)&xr, g_xr);
    float* ssp;  cudaGetSymbolAddress((void**)&ssp, g_ss);
    float* sdp;  cudaGetSymbolAddress((void**)&sdp, g_sd);
    __nv_bfloat16* hb; cudaGetSymbolAddress((void**)&hb, g_hb);

    const int ggrid = (NN + 127) / 128;

    // 1: layer-1 transform (+scores, +bf16 copy)
    gemm_tc_kernel<true, true><<<ggrid, 256>>>(x, W1, a1s, a1d, bufA, hb, ssp, sdp);
    // 2-4: preprocessing (scatter in profile slot 4)
    count_kernel<<<(EE + 255) / 256, 256>>>(ei);
    scan_fused<<<NB_SCAN, 256>>>();
    scatter_kernel<<<(EE + 255) / 256, 256>>>(ei);
    // 5: layer-1 aggregation (bf16 gather)
    agg_kernel<1><<<(NN + 7) / 8, 256>>>(hb, ssp, sdp, b1, bufB, nullptr, nullptr);
    // 6: layer-2 transform (+scores, +bf16 copy)
    gemm_tc_kernel<true, true><<<ggrid, 256>>>(bufB, W2, a2s, a2d, bufA, hb, ssp, sdp);
    // 7: residual transform
    gemm_tc_kernel<false, false><<<ggrid, 256>>>(x, Wr, nullptr, nullptr,
                                                 xr, nullptr, nullptr, nullptr);
    // 8: layer-2 aggregation + residual (+ deg reset)
    agg_kernel<2><<<(NN + 7) / 8, 256>>>(hb, ssp, sdp, b2, out, xr, br);
}

// round 9
// speedup vs baseline: 1.2055x; 1.0709x over previous
#include <cuda_runtime.h>
#include <cuda_bf16.h>
#include <math.h>
#include <stdint.h>

#define NN 100000
#define EE 1600000
#define D  128
#define HEADS 4
#define CH 32
#define NEG_SLOPE 0.2f
#define CAP 64                         // deg ~ Poisson(16); P(deg>64) ~ 2e-22
#define NB_SCAN ((NN + 1023) / 1024)   // 98 blocks (single wave)

// ---------------- scratch ------------------------------------------------------
__device__ __nv_bfloat16 g_hb[NN * D];    // current layer h (gather source)
__device__ __nv_bfloat16 g_hb2[NN * D];   // relu(h1) bf16 (GEMM2 input)
__device__ float g_xr[NN * D];
__device__ float g_ss[NN * HEADS];
__device__ float g_sd[NN * HEADS];
__device__ int   g_deg[NN];
__device__ int   g_offs[NN + 1];
__device__ int   g_cursor[NN];
__device__ int   g_sorted_src[EE];
__device__ int   g_bsum[NB_SCAN];
__device__ unsigned g_bar_count = 0;
__device__ volatile unsigned g_bar_gen = 0;

__device__ __forceinline__ void gbar_scan() {
    __syncthreads();
    if (threadIdx.x == 0) {
        __threadfence();
        unsigned gen = g_bar_gen;
        if (atomicAdd(&g_bar_count, 1u) == NB_SCAN - 1) {
            g_bar_count = 0;
            __threadfence();
            g_bar_gen = gen + 1;
        } else {
            while (g_bar_gen == gen) { }
        }
        __threadfence();
    }
    __syncthreads();
}

// ---------------- edge dtype detection (per-block inline) -----------------------
__device__ __forceinline__ int detect_s64(const void* ei, int* smem_flag) {
    if (threadIdx.x == 0) *smem_flag = 1;
    __syncthreads();
    if (threadIdx.x < 256)
        if (((const unsigned int*)ei)[2 * threadIdx.x + 1] != 0u) *smem_flag = 0;
    __syncthreads();
    return *smem_flag;
}

// ---------------- counting sort --------------------------------------------------
__global__ void __launch_bounds__(256) count_kernel(const void* __restrict__ ei) {
    __shared__ int s64s;
    int s64 = detect_s64(ei, &s64s);
    int i = blockIdx.x * blockDim.x + threadIdx.x;
    if (i >= EE) return;
    int d = s64 ? (int)((const long long*)ei)[(long long)EE + i]
                : ((const int*)ei)[EE + i];
    atomicAdd(&g_deg[d], 1);
}

__global__ void __launch_bounds__(256) scan_fused() {
    __shared__ int sm[256];
    __shared__ int blockpre;
    int b = blockIdx.x, tid = threadIdx.x;
    int base = b * 1024 + tid * 4;

    int v[4];
#pragma unroll
    for (int j = 0; j < 4; ++j) {
        int idx = base + j;
        v[j] = (idx < NN) ? g_deg[idx] : 0;
    }
    int tot = v[0] + v[1] + v[2] + v[3];

    sm[tid] = tot;
    __syncthreads();
    for (int off = 128; off; off >>= 1) {
        if (tid < off) sm[tid] += sm[tid + off];
        __syncthreads();
    }
    if (tid == 0) g_bsum[b] = sm[0];

    gbar_scan();

    if (tid == 0) {
        int p = 0;
        for (int i = 0; i < b; ++i) p += g_bsum[i];
        blockpre = p;
    }
    sm[tid] = tot;
    __syncthreads();
    for (int off = 1; off < 256; off <<= 1) {
        int x = (tid >= off) ? sm[tid - off] : 0;
        __syncthreads();
        sm[tid] += x;
        __syncthreads();
    }
    int run = blockpre + ((tid == 0) ? 0 : sm[tid - 1]);
#pragma unroll
    for (int j = 0; j < 4; ++j) {
        int idx = base + j;
        if (idx < NN) {
            g_offs[idx]   = run;
            g_cursor[idx] = run;
            run += v[j];
        }
    }
    if (b == 0 && tid == 0) g_offs[NN] = EE;
}

__global__ void __launch_bounds__(256) scatter_kernel(const void* __restrict__ ei) {
    __shared__ int s64s;
    int s64 = detect_s64(ei, &s64s);
    int i = blockIdx.x * blockDim.x + threadIdx.x;
    if (i >= EE) return;
    int s, d;
    if (s64) {
        s = (int)((const long long*)ei)[i];
        d = (int)((const long long*)ei)[(long long)EE + i];
    } else {
        s = ((const int*)ei)[i];
        d = ((const int*)ei)[EE + i];
    }
    int pos = atomicAdd(&g_cursor[d], 1);
    g_sorted_src[pos] = s;
}

// ---------------- tf32 MMA helpers ------------------------------------------------
__device__ __forceinline__ uint32_t to_tf32u(float x) {
    uint32_t u;
    asm("cvt.rna.tf32.f32 %0, %1;" : "=r"(u) : "f"(x));
    return u;
}
__device__ __forceinline__ void cp16(uint32_t smem_dst, const void* gsrc) {
    asm volatile("cp.async.cg.shared.global [%0], [%1], 16;\n"
                 :: "r"(smem_dst), "l"(gsrc));
}
#define CP_COMMIT()  asm volatile("cp.async.commit_group;\n" ::: "memory")
#define CP_WAIT_1()  asm volatile("cp.async.wait_group 1;\n" ::: "memory")
#define CP_WAIT_0()  asm volatile("cp.async.wait_group 0;\n" ::: "memory")

#define MMA_TF32(c, av, bv)                                                  \
    asm volatile(                                                            \
        "mma.sync.aligned.m16n8k8.row.col.f32.tf32.tf32.f32 "                \
        "{%0,%1,%2,%3},{%4,%5,%6,%7},{%8,%9},{%0,%1,%2,%3};"                 \
        : "+f"((c)[0]), "+f"((c)[1]), "+f"((c)[2]), "+f"((c)[3])             \
        : "r"((av)[0]), "r"((av)[1]), "r"((av)[2]), "r"((av)[3]),            \
          "r"((bv)[0]), "r"((bv)[1]))

#define KC 16
#define NCH (D / KC)

// ---- dual GEMM: [x@W1 -> bf16 hb + scores | x@Wr -> fp32 xr], pipelined ---------
// 512 thr = 16 warps as 4(M) x 4(N); block tile 128 x 256; warp tile 32 x 64
#define DUAL_SMEM ((2 * 128 * 20 + 2 * KC * 264) * 4)   // 54272 B (dynamic)
__global__ void __launch_bounds__(512, 1) gemm_dual_kernel(
    const float* __restrict__ A,
    const float* __restrict__ W1, const float* __restrict__ Wr,
    const float* __restrict__ a_src, const float* __restrict__ a_dst,
    __nv_bfloat16* __restrict__ hb, float* __restrict__ xr,
    float* __restrict__ ssrc, float* __restrict__ sdst)
{
    extern __shared__ float dsm[];
    float* As = dsm;                    // [2][128][20]
    float* Ws = dsm + 2 * 128 * 20;     // [2][KC][264]; cols 0-127=W1, 128-255=Wr

    const int tid  = threadIdx.x;
    const int warp = tid >> 5, lane = tid & 31;
    const int g = lane >> 2, t = lane & 3;
    const int wm = warp >> 2;          // 0..3
    const int wn = warp & 3;           // 0..3 ; wn<2 -> W1/heads, wn>=2 -> Wr
    const int m0 = wm * 32, n0 = wn * 64;
    const int row0 = blockIdx.x * 128;

    const uint32_t as_base = (uint32_t)__cvta_generic_to_shared(As);
    const uint32_t ws_base = (uint32_t)__cvta_generic_to_shared(Ws);

    float acc[2][8][4];
#pragma unroll
    for (int i = 0; i < 2; ++i)
#pragma unroll
        for (int j = 0; j < 8; ++j)
#pragma unroll
            for (int k = 0; k < 4; ++k) acc[i][j][k] = 0.f;

    auto load_stage = [&](int s, int kc) {
        {   // A: 512 16B chunks
            int r = tid >> 2, q = tid & 3;
            int row = row0 + r; if (row >= NN) row = NN - 1;
            cp16(as_base + (uint32_t)(((s * 128 + r) * 20 + q * 4) * 4),
                 &A[(long long)row * D + kc + q * 4]);
        }
#pragma unroll
        for (int it = 0; it < 2; ++it) {   // W: 1024 16B chunks
            int idx = tid + it * 512;
            int kr = idx >> 6, c4 = idx & 63;
            const float* src = (c4 < 32) ? &W1[(kc + kr) * D + c4 * 4]
                                         : &Wr[(kc + kr) * D + (c4 - 32) * 4];
            cp16(ws_base + (uint32_t)(((s * KC + kr) * 264 + c4 * 4) * 4), src);
        }
    };

    load_stage(0, 0);
    CP_COMMIT();

    for (int c = 0; c < NCH; ++c) {
        const int cur = c & 1;
        if (c + 1 < NCH) {
            load_stage((c + 1) & 1, (c + 1) * KC);
            CP_COMMIT();
            CP_WAIT_1();
        } else {
            CP_WAIT_0();
        }
        __syncthreads();

#pragma unroll
        for (int ks = 0; ks < KC; ks += 8) {
            uint32_t a[2][4], b[8][2];
#pragma unroll
            for (int mt = 0; mt < 2; ++mt) {
                int row = cur * 128 + m0 + mt * 16 + g;
                a[mt][0] = to_tf32u(As[row * 20 + ks + t]);
                a[mt][1] = to_tf32u(As[(row + 8) * 20 + ks + t]);
                a[mt][2] = to_tf32u(As[row * 20 + ks + t + 4]);
                a[mt][3] = to_tf32u(As[(row + 8) * 20 + ks + t + 4]);
            }
#pragma unroll
            for (int nt = 0; nt < 8; ++nt) {
                int nc = n0 + nt * 8 + g;
                b[nt][0] = to_tf32u(Ws[(cur * KC + ks + t) * 264 + nc]);
                b[nt][1] = to_tf32u(Ws[(cur * KC + ks + t + 4) * 264 + nc]);
            }
#pragma unroll
            for (int mt = 0; mt < 2; ++mt)
#pragma unroll
                for (int nt = 0; nt < 8; ++nt)
                    MMA_TF32(acc[mt][nt], a[mt], b[nt]);
        }
        __syncthreads();
    }

    const bool is1 = (wn < 2);
    const int h0 = 2 * wn, h1 = 2 * wn + 1;   // valid when is1
    float2 asv[8], adv[8];
    if (is1) {
#pragma unroll
        for (int nt = 0; nt < 8; ++nt) {
            int head = (nt < 4) ? h0 : h1;
            int cch  = (nt & 3) * 8 + 2 * t;
            asv[nt] = make_float2(a_src[head * CH + cch], a_src[head * CH + cch + 1]);
            adv[nt] = make_float2(a_dst[head * CH + cch], a_dst[head * CH + cch + 1]);
        }
    }
#pragma unroll
    for (int mt = 0; mt < 2; ++mt) {
        int r_lo = row0 + m0 + mt * 16 + g;
        int r_hi = r_lo + 8;
        float sA_lo = 0.f, dA_lo = 0.f, sA_hi = 0.f, dA_hi = 0.f;
        float sB_lo = 0.f, dB_lo = 0.f, sB_hi = 0.f, dB_hi = 0.f;
#pragma unroll
        for (int nt = 0; nt < 8; ++nt) {
            float2 v_lo = make_float2(acc[mt][nt][0], acc[mt][nt][1]);
            float2 v_hi = make_float2(acc[mt][nt][2], acc[mt][nt][3]);
            if (is1) {
                int col = n0 + nt * 8 + 2 * t;
                if (r_lo < NN)
                    *(__nv_bfloat162*)&hb[(long long)r_lo * D + col] =
                        __float22bfloat162_rn(v_lo);
                if (r_hi < NN)
                    *(__nv_bfloat162*)&hb[(long long)r_hi * D + col] =
                        __float22bfloat162_rn(v_hi);
                sA_lo += (nt < 4) ? 0.f : 0.f;   // (kept structure below)
                float su_l = v_lo.x * asv[nt].x + v_lo.y * asv[nt].y;
                float du_l = v_lo.x * adv[nt].x + v_lo.y * adv[nt].y;
                float su_h = v_hi.x * asv[nt].x + v_hi.y * asv[nt].y;
                float du_h = v_hi.x * adv[nt].x + v_hi.y * adv[nt].y;
                if (nt < 4) { sA_lo += su_l; dA_lo += du_l; sA_hi += su_h; dA_hi += du_h; }
                else        { sB_lo += su_l; dB_lo += du_l; sB_hi += su_h; dB_hi += du_h; }
            } else {
                int colr = n0 - 128 + nt * 8 + 2 * t;
                if (r_lo < NN) *(float2*)&xr[(long long)r_lo * D + colr] = v_lo;
                if (r_hi < NN) *(float2*)&xr[(long long)r_hi * D + colr] = v_hi;
            }
        }
        if (is1) {
#pragma unroll
            for (int off = 1; off <= 2; off <<= 1) {
                sA_lo += __shfl_xor_sync(0xffffffffu, sA_lo, off);
                dA_lo += __shfl_xor_sync(0xffffffffu, dA_lo, off);
                sA_hi += __shfl_xor_sync(0xffffffffu, sA_hi, off);
                dA_hi += __shfl_xor_sync(0xffffffffu, dA_hi, off);
                sB_lo += __shfl_xor_sync(0xffffffffu, sB_lo, off);
                dB_lo += __shfl_xor_sync(0xffffffffu, dB_lo, off);
                sB_hi += __shfl_xor_sync(0xffffffffu, sB_hi, off);
                dB_hi += __shfl_xor_sync(0xffffffffu, dB_hi, off);
            }
            if (t == 0) {
                if (r_lo < NN) {
                    ssrc[r_lo * HEADS + h0] = sA_lo; sdst[r_lo * HEADS + h0] = dA_lo;
                    ssrc[r_lo * HEADS + h1] = sB_lo; sdst[r_lo * HEADS + h1] = dB_lo;
                }
                if (r_hi < NN) {
                    ssrc[r_hi * HEADS + h0] = sA_hi; sdst[r_hi * HEADS + h0] = dA_hi;
                    ssrc[r_hi * HEADS + h1] = sB_hi; sdst[r_hi * HEADS + h1] = dB_hi;
                }
            }
        }
    }
}

// ---- layer-2 GEMM: bf16 input (exact in tf32), bf16 output + scores -------------
// 256 thr = 8 warps as 4(M) x 2(N); block tile 128 x 128; warp tile 32 x 64
__global__ void __launch_bounds__(256, 2) gemm_l2_kernel(
    const unsigned short* __restrict__ A,   // bf16 raw bits
    const float* __restrict__ W,
    const float* __restrict__ a_src, const float* __restrict__ a_dst,
    __nv_bfloat16* __restrict__ hb,
    float* __restrict__ ssrc, float* __restrict__ sdst)
{
    __shared__ unsigned short As[2][128][24];   // bf16, pitch 24 (48B, 16B-aligned)
    __shared__ float Ws[2][KC][132];

    const int tid  = threadIdx.x;
    const int warp = tid >> 5, lane = tid & 31;
    const int g = lane >> 2, t = lane & 3;
    const int wm = warp >> 1;
    const int wn = warp & 1;
    const int m0 = wm * 32, n0 = wn * 64;
    const int row0 = blockIdx.x * 128;

    const uint32_t as_base = (uint32_t)__cvta_generic_to_shared(&As[0][0][0]);
    const uint32_t ws_base = (uint32_t)__cvta_generic_to_shared(&Ws[0][0][0]);

    float acc[2][8][4];
#pragma unroll
    for (int i = 0; i < 2; ++i)
#pragma unroll
        for (int j = 0; j < 8; ++j)
#pragma unroll
            for (int k = 0; k < 4; ++k) acc[i][j][k] = 0.f;

    auto load_stage = [&](int s, int kc) {
        {   // A: 256 16B chunks (8 bf16 each)
            int r = tid >> 1, q = tid & 1;
            int row = row0 + r; if (row >= NN) row = NN - 1;
            cp16(as_base + (uint32_t)(((s * 128 + r) * 24 + q * 8) * 2),
                 &A[(long long)row * D + kc + q * 8]);
        }
#pragma unroll
        for (int it = 0; it < 2; ++it) {   // W: 512 16B chunks
            int idx = tid + it * 256;
            int kr = idx >> 5, c4 = idx & 31;
            cp16(ws_base + (uint32_t)(((s * KC + kr) * 132 + c4 * 4) * 4),
                 &W[(kc + kr) * D + c4 * 4]);
        }
    };

    load_stage(0, 0);
    CP_COMMIT();

    for (int c = 0; c < NCH; ++c) {
        const int cur = c & 1;
        if (c + 1 < NCH) {
            load_stage((c + 1) & 1, (c + 1) * KC);
            CP_COMMIT();
            CP_WAIT_1();
        } else {
            CP_WAIT_0();
        }
        __syncthreads();

#pragma unroll
        for (int ks = 0; ks < KC; ks += 8) {
            uint32_t a[2][4], b[8][2];
#pragma unroll
            for (int mt = 0; mt < 2; ++mt) {
                int row = m0 + mt * 16 + g;
                a[mt][0] = ((uint32_t)As[cur][row][ks + t]) << 16;
                a[mt][1] = ((uint32_t)As[cur][row + 8][ks + t]) << 16;
                a[mt][2] = ((uint32_t)As[cur][row][ks + t + 4]) << 16;
                a[mt][3] = ((uint32_t)As[cur][row + 8][ks + t + 4]) << 16;
            }
#pragma unroll
            for (int nt = 0; nt < 8; ++nt) {
                int nc = n0 + nt * 8 + g;
                b[nt][0] = to_tf32u(Ws[cur][ks + t][nc]);
                b[nt][1] = to_tf32u(Ws[cur][ks + t + 4][nc]);
            }
#pragma unroll
            for (int mt = 0; mt < 2; ++mt)
#pragma unroll
                for (int nt = 0; nt < 8; ++nt)
                    MMA_TF32(acc[mt][nt], a[mt], b[nt]);
        }
        __syncthreads();
    }

    const int h0 = 2 * wn, h1 = 2 * wn + 1;
    float2 asv[8], adv[8];
#pragma unroll
    for (int nt = 0; nt < 8; ++nt) {
        int head = (nt < 4) ? h0 : h1;
        int cch  = (nt & 3) * 8 + 2 * t;
        asv[nt] = make_float2(a_src[head * CH + cch], a_src[head * CH + cch + 1]);
        adv[nt] = make_float2(a_dst[head * CH + cch], a_dst[head * CH + cch + 1]);
    }
#pragma unroll
    for (int mt = 0; mt < 2; ++mt) {
        int r_lo = row0 + m0 + mt * 16 + g;
        int r_hi = r_lo + 8;
        float sA_lo = 0.f, dA_lo = 0.f, sA_hi = 0.f, dA_hi = 0.f;
        float sB_lo = 0.f, dB_lo = 0.f, sB_hi = 0.f, dB_hi = 0.f;
#pragma unroll
        for (int nt = 0; nt < 8; ++nt) {
            int col = n0 + nt * 8 + 2 * t;
            float2 v_lo = make_float2(acc[mt][nt][0], acc[mt][nt][1]);
            float2 v_hi = make_float2(acc[mt][nt][2], acc[mt][nt][3]);
            if (r_lo < NN)
                *(__nv_bfloat162*)&hb[(long long)r_lo * D + col] =
                    __float22bfloat162_rn(v_lo);
            if (r_hi < NN)
                *(__nv_bfloat162*)&hb[(long long)r_hi * D + col] =
                    __float22bfloat162_rn(v_hi);
            float su_l = v_lo.x * asv[nt].x + v_lo.y * asv[nt].y;
            float du_l = v_lo.x * adv[nt].x + v_lo.y * adv[nt].y;
            float su_h = v_hi.x * asv[nt].x + v_hi.y * asv[nt].y;
            float du_h = v_hi.x * adv[nt].x + v_hi.y * adv[nt].y;
            if (nt < 4) { sA_lo += su_l; dA_lo += du_l; sA_hi += su_h; dA_hi += du_h; }
            else        { sB_lo += su_l; dB_lo += du_l; sB_hi += su_h; dB_hi += du_h; }
        }
#pragma unroll
        for (int off = 1; off <= 2; off <<= 1) {
            sA_lo += __shfl_xor_sync(0xffffffffu, sA_lo, off);
            dA_lo += __shfl_xor_sync(0xffffffffu, dA_lo, off);
            sA_hi += __shfl_xor_sync(0xffffffffu, sA_hi, off);
            dA_hi += __shfl_xor_sync(0xffffffffu, dA_hi, off);
            sB_lo += __shfl_xor_sync(0xffffffffu, sB_lo, off);
            dB_lo += __shfl_xor_sync(0xffffffffu, dB_lo, off);
            sB_hi += __shfl_xor_sync(0xffffffffu, sB_hi, off);
            dB_hi += __shfl_xor_sync(0xffffffffu, dB_hi, off);
        }
        if (t == 0) {
            if (r_lo < NN) {
                ssrc[r_lo * HEADS + h0] = sA_lo; sdst[r_lo * HEADS + h0] = dA_lo;
                ssrc[r_lo * HEADS + h1] = sB_lo; sdst[r_lo * HEADS + h1] = dB_lo;
            }
            if (r_hi < NN) {
                ssrc[r_hi * HEADS + h0] = sA_hi; sdst[r_hi * HEADS + h0] = dA_hi;
                ssrc[r_hi * HEADS + h1] = sB_hi; sdst[r_hi * HEADS + h1] = dB_hi;
            }
        }
    }
}

// ---------------- softmax + aggregation -------------------------------------------
__device__ __forceinline__ float lrelu(float v) { return v > 0.f ? v : NEG_SLOPE * v; }

template<int LAYER>
__global__ void __launch_bounds__(256) agg_kernel(
    const __nv_bfloat16* __restrict__ hb,
    const float* __restrict__ ss,
    const float* __restrict__ sd,
    const float* __restrict__ bias,
    float* __restrict__ outf,              // LAYER 2
    __nv_bfloat16* __restrict__ outb,      // LAYER 1
    const float* __restrict__ xr,
    const float* __restrict__ br)
{
    __shared__ float2 pse[8][HEADS][CAP];

    int warp = (blockIdx.x * blockDim.x + threadIdx.x) >> 5;
    int wip  = threadIdx.x >> 5;
    int lane = threadIdx.x & 31;
    if (warp >= NN) return;
    int n = warp;
    int begin = g_offs[n], end = g_offs[n + 1];
    int deg = end - begin;
    if (LAYER == 2 && lane == 0) g_deg[n] = 0;   // reset for next replay

    float4 sdv = *(const float4*)&sd[n * HEADS];
    float4 ssn = *(const float4*)&ss[n * HEADS];
    float es0 = __expf(lrelu(ssn.x + sdv.x));
    float es1 = __expf(lrelu(ssn.y + sdv.y));
    float es2 = __expf(lrelu(ssn.z + sdv.z));
    float es3 = __expf(lrelu(ssn.w + sdv.w));
    float d0 = 0.f, d1 = 0.f, d2 = 0.f, d3 = 0.f;

    int hd = lane >> 3;
    int c0 = lane * 4;

    auto gather4 = [&](int s, float& vx, float& vy, float& vz, float& vw) {
        uint2 u = *(const uint2*)&hb[(long long)s * D + c0];
        __nv_bfloat162 p0 = *reinterpret_cast<__nv_bfloat162*>(&u.x);
        __nv_bfloat162 p1 = *reinterpret_cast<__nv_bfloat162*>(&u.y);
        float2 f0 = __bfloat1622float2(p0);
        float2 f1 = __bfloat1622float2(p1);
        vx = f0.x; vy = f0.y; vz = f1.x; vw = f1.y;
    };

    float ax, ay, az, aw;
    float inv_dh;

    if (deg <= CAP) {
        for (int i = lane; i < deg; i += 32) {
            int s = g_sorted_src[begin + i];
            float4 sv = *(const float4*)&ss[s * HEADS];
            float fs = __int_as_float(s);
            float e0 = __expf(lrelu(sv.x + sdv.x));
            float e1 = __expf(lrelu(sv.y + sdv.y));
            float e2 = __expf(lrelu(sv.z + sdv.z));
            float e3 = __expf(lrelu(sv.w + sdv.w));
            pse[wip][0][i] = make_float2(fs, e0);
            pse[wip][1][i] = make_float2(fs, e1);
            pse[wip][2][i] = make_float2(fs, e2);
            pse[wip][3][i] = make_float2(fs, e3);
            d0 += e0; d1 += e1; d2 += e2; d3 += e3;
        }
#pragma unroll
        for (int off = 16; off; off >>= 1) {
            d0 += __shfl_xor_sync(0xffffffffu, d0, off);
            d1 += __shfl_xor_sync(0xffffffffu, d1, off);
            d2 += __shfl_xor_sync(0xffffffffu, d2, off);
            d3 += __shfl_xor_sync(0xffffffffu, d3, off);
        }
        d0 += es0; d1 += es1; d2 += es2; d3 += es3;
        __syncwarp();

        float dh  = (hd == 0) ? d0 : (hd == 1) ? d1 : (hd == 2) ? d2 : d3;
        float esh = (hd == 0) ? es0 : (hd == 1) ? es1 : (hd == 2) ? es2 : es3;
        inv_dh = 1.f / dh;

        float hx, hy, hz, hw;
        gather4(n, hx, hy, hz, hw);
        ax = esh * hx; ay = esh * hy; az = esh * hz; aw = esh * hw;

        const float2* __restrict__ pp = &pse[wip][hd][0];
#pragma unroll 8
        for (int i = 0; i < deg; ++i) {
            float2 p = pp[i];
            int s = __float_as_int(p.x);
            float e = p.y;
            float vx, vy, vz, vw;
            gather4(s, vx, vy, vz, vw);
            ax += e * vx; ay += e * vy; az += e * vz; aw += e * vw;
        }
    } else {
        // fallback (deg > CAP; statistically unreachable)
        for (int e = begin + lane; e < end; e += 32) {
            int s = g_sorted_src[e];
            float4 sv = *(const float4*)&ss[s * HEADS];
            d0 += __expf(lrelu(sv.x + sdv.x));
            d1 += __expf(lrelu(sv.y + sdv.y));
            d2 += __expf(lrelu(sv.z + sdv.z));
            d3 += __expf(lrelu(sv.w + sdv.w));
        }
#pragma unroll
        for (int off = 16; off; off >>= 1) {
            d0 += __shfl_xor_sync(0xffffffffu, d0, off);
            d1 += __shfl_xor_sync(0xffffffffu, d1, off);
            d2 += __shfl_xor_sync(0xffffffffu, d2, off);
            d3 += __shfl_xor_sync(0xffffffffu, d3, off);
        }
        d0 += es0; d1 += es1; d2 += es2; d3 += es3;

        float dh  = (hd == 0) ? d0 : (hd == 1) ? d1 : (hd == 2) ? d2 : d3;
        float esh = (hd == 0) ? es0 : (hd == 1) ? es1 : (hd == 2) ? es2 : es3;
        float sdh = (hd == 0) ? sdv.x : (hd == 1) ? sdv.y : (hd == 2) ? sdv.z : sdv.w;
        inv_dh = 1.f / dh;

        float hx, hy, hz, hw;
        gather4(n, hx, hy, hz, hw);
        ax = esh * hx; ay = esh * hy; az = esh * hz; aw = esh * hw;
        for (int e = begin; e < end; ++e) {
            int s = g_sorted_src[e];
            float w = __expf(lrelu(ss[s * HEADS + hd] + sdh));
            float vx, vy, vz, vw;
            gather4(s, vx, vy, vz, vw);
            ax += w * vx; ay += w * vy; az += w * vz; aw += w * vw;
        }
    }

    ax *= inv_dh; ay *= inv_dh; az *= inv_dh; aw *= inv_dh;

    float4 b = *(const float4*)&bias[c0];
    if (LAYER == 1) {
        float ox = fmaxf(ax + b.x, 0.f), oy = fmaxf(ay + b.y, 0.f);
        float oz = fmaxf(az + b.z, 0.f), ow = fmaxf(aw + b.w, 0.f);
        __nv_bfloat162 p0 = __float22bfloat162_rn(make_float2(ox, oy));
        __nv_bfloat162 p1 = __float22bfloat162_rn(make_float2(oz, ow));
        uint2 u;
        u.x = *reinterpret_cast<uint32_t*>(&p0);
        u.y = *reinterpret_cast<uint32_t*>(&p1);
        *(uint2*)&outb[(long long)n * D + c0] = u;
    } else {
        float4 r  = *(const float4*)&xr[(long long)n * D + c0];
        float4 bb = *(const float4*)&br[c0];
        float4 o = make_float4(ax + b.x + r.x + bb.x, ay + b.y + r.y + bb.y,
                               az + b.z + r.z + bb.z, aw + b.w + r.w + bb.w);
        *(float4*)&outf[(long long)n * D + c0] = o;
    }
}

// ---------------- launch ----------------------------------------------------------
extern "C" void kernel_launch(void* const* d_in, const int* in_sizes, int n_in,
                              void* d_out, int out_size) {
    const float* x   = (const float*)d_in[0];
    const void*  ei  = d_in[1];
    const float* W1  = (const float*)d_in[2];
    const float* a1s = (const float*)d_in[3];
    const float* a1d = (const float*)d_in[4];
    const float* b1  = (const float*)d_in[5];
    const float* W2  = (const float*)d_in[6];
    const float* a2s = (const float*)d_in[7];
    const float* a2d = (const float*)d_in[8];
    const float* b2  = (const float*)d_in[9];
    const float* Wr  = (const float*)d_in[10];
    const float* br  = (const float*)d_in[11];
    float* out = (float*)d_out;

    float* xr;   cudaGetSymbolAddress((void**)&xr, g_xr);
    float* ssp;  cudaGetSymbolAddress((void**)&ssp, g_ss);
    float* sdp;  cudaGetSymbolAddress((void**)&sdp, g_sd);
    __nv_bfloat16* hb;  cudaGetSymbolAddress((void**)&hb, g_hb);
    __nv_bfloat16* hb2; cudaGetSymbolAddress((void**)&hb2, g_hb2);

    static bool attr_set = false;
    if (!attr_set) {
        cudaFuncSetAttribute(gemm_dual_kernel,
                             cudaFuncAttributeMaxDynamicSharedMemorySize, DUAL_SMEM);
        attr_set = true;
    }

    const int ggrid = (NN + 127) / 128;

    // 1: layer-1 + residual transform (x read once; bf16 h1 + scores; fp32 xr)
    gemm_dual_kernel<<<ggrid, 512, DUAL_SMEM>>>(x, W1, Wr, a1s, a1d,
                                                hb, xr, ssp, sdp);
    // 2-4: edge preprocessing
    count_kernel<<<(EE + 255) / 256, 256>>>(ei);
    scan_fused<<<NB_SCAN, 256>>>();
    scatter_kernel<<<(EE + 255) / 256, 256>>>(ei);
    // 5: layer-1 aggregation -> relu(h1) in bf16
    agg_kernel<1><<<(NN + 7) / 8, 256>>>(hb, ssp, sdp, b1, nullptr, hb2,
                                         nullptr, nullptr);
    // 6: layer-2 transform (bf16 in, bf16 out + scores)
    gemm_l2_kernel<<<ggrid, 256>>>((const unsigned short*)hb2, W2, a2s, a2d,
                                   hb, ssp, sdp);
    // 7: layer-2 aggregation + residual (+ deg reset)
    agg_kernel<2><<<(NN + 7) / 8, 256>>>(hb, ssp, sdp, b2, out, nullptr, xr, br);
}